// round 4
// baseline (speedup 1.0000x reference)
#include <cuda_runtime.h>
#include <cuda_bf16.h>
#include <math.h>
#include <stdint.h>

// Problem constants
#define BB   2
#define TT   2048
#define CC   1024
#define HH   16
#define KVH  4
#define DH   64
#define NREP 4
#define FF   4096
#define EE   8
#define TOPK 2
#define WIN  1024
#define NTOK (BB*TT)            // 4096
#define OUT_MAIN (NTOK*CC)      // 4194304

// ---------------- scratch (device globals; no allocation) ----------------
__device__ float g_q   [NTOK*CC];
__device__ float g_k   [NTOK*KVH*DH];
__device__ float g_v   [NTOK*KVH*DH];
__device__ float g_proj[NTOK*CC];
__device__ float g_h   [NTOK*CC];
__device__ float g_xf  [NTOK*CC];
__device__ float g_moe [NTOK*CC];
__device__ float g_g1  [NTOK*FF];
__device__ float g_g2  [NTOK*FF];
__device__ float g_eo  [NTOK*CC];
__device__ float g_probs[NTOK*EE];
__device__ float g_lse2[NTOK];
__device__ int   g_sel [NTOK*2];
__device__ float g_selw[NTOK*2];
__device__ int   g_cnt [EE];
__device__ int   g_idx [EE*NTOK];
__device__ float g_w   [EE*NTOK];
__device__ float g_aux;

// bf16 activations
__device__ __nv_bfloat16 g_xnb [NTOK*CC];
__device__ __nv_bfloat16 g_aob [NTOK*CC];
__device__ __nv_bfloat16 g_xfb [NTOK*CC];
__device__ __nv_bfloat16 g_xgb [NTOK*CC];
__device__ __nv_bfloat16 g_g1b [NTOK*FF];

// bf16 transposed weights [N,K]
__device__ __nv_bfloat16 g_wqt [CC*CC];
__device__ __nv_bfloat16 g_wkt [KVH*DH*CC];
__device__ __nv_bfloat16 g_wvt [KVH*DH*CC];
__device__ __nv_bfloat16 g_wot [CC*CC];
__device__ __nv_bfloat16 g_sw1t[FF*CC];
__device__ __nv_bfloat16 g_sw2t[FF*CC];
__device__ __nv_bfloat16 g_sw3t[CC*FF];
__device__ __nv_bfloat16 g_ew1t[EE*FF*CC];
__device__ __nv_bfloat16 g_ew2t[EE*FF*CC];
__device__ __nv_bfloat16 g_ew3t[EE*CC*FF];

__device__ __forceinline__ uint32_t su32(const void* p) {
    uint32_t a;
    asm("{ .reg .u64 t; cvta.to.shared.u64 t, %1; cvt.u32.u64 %0, t; }" : "=r"(a) : "l"(p));
    return a;
}

#define CP_ASYNC16(d, s) asm volatile("cp.async.cg.shared.global [%0], [%1], 16;" :: "r"(d), "l"(s))
#define CP_COMMIT()      asm volatile("cp.async.commit_group;" ::: "memory")
#define CP_WAIT(n)       asm volatile("cp.async.wait_group %0;" :: "n"(n) : "memory")

// ================= bf16 mma.sync GEMM: C[M,N] = A[M,K] @ W[K,N] =========
// A: bf16 [M,K] row-major. Bt: bf16 [N,K] row-major (pre-transposed weight).
// CTA tile 128x128, BK=32, 8 warps (2x4), warp tile 64x32.
#define BM 128
#define BN 128
#define BK 32
#define ASTR 40   // padded row stride in bf16 elems (80 bytes)

__global__ __launch_bounds__(256) void gemm_mma(
    const __nv_bfloat16* __restrict__ A, const __nv_bfloat16* __restrict__ Bt,
    float* __restrict__ C, int M, int N, int K, const int* mPtr)
{
    int Meff = mPtr ? *mPtr : M;
    int rowBase = blockIdx.y * BM;
    if (rowBase >= Meff) return;
    int colBase = blockIdx.x * BN;

    __shared__ __align__(16) __nv_bfloat16 sA[2][BM * ASTR];
    __shared__ __align__(16) __nv_bfloat16 sB[2][BM * ASTR];

    int tid = threadIdx.x;
    int wid = tid >> 5, lane = tid & 31;
    int wm = wid >> 2, wn = wid & 3;

    float cr[4][4][4];
#pragma unroll
    for (int i = 0; i < 4; i++)
#pragma unroll
        for (int j = 0; j < 4; j++)
#pragma unroll
            for (int r = 0; r < 4; r++) cr[i][j][r] = 0.f;

    int lrow = tid >> 1;              // 0..127
    int lc16 = (tid & 1) * 16;        // 0 or 16 (two 8-elem vectors per half-row)

    int nCh = K / BK;

    // prefetch stage 0
    {
        const __nv_bfloat16* srcA0 = A + (size_t)(rowBase + lrow) * K + lc16;
        const __nv_bfloat16* srcB0 = Bt + (size_t)(colBase + lrow) * K + lc16;
        uint32_t dA0 = su32(&sA[0][lrow * ASTR + lc16]);
        uint32_t dB0 = su32(&sB[0][lrow * ASTR + lc16]);
        CP_ASYNC16(dA0, srcA0);
        CP_ASYNC16(dA0 + 16, srcA0 + 8);
        CP_ASYNC16(dB0, srcB0);
        CP_ASYNC16(dB0 + 16, srcB0 + 8);
        CP_COMMIT();
    }

    for (int ch = 0; ch < nCh; ch++) {
        int st = ch & 1;
        if (ch + 1 < nCh) {
            int k0 = (ch + 1) * BK;
            const __nv_bfloat16* srcA = A + (size_t)(rowBase + lrow) * K + k0 + lc16;
            const __nv_bfloat16* srcB = Bt + (size_t)(colBase + lrow) * K + k0 + lc16;
            uint32_t dA = su32(&sA[st ^ 1][lrow * ASTR + lc16]);
            uint32_t dB = su32(&sB[st ^ 1][lrow * ASTR + lc16]);
            CP_ASYNC16(dA, srcA);
            CP_ASYNC16(dA + 16, srcA + 8);
            CP_ASYNC16(dB, srcB);
            CP_ASYNC16(dB + 16, srcB + 8);
            CP_COMMIT();
            CP_WAIT(1);
        } else {
            CP_WAIT(0);
        }
        __syncthreads();

        int r16 = lane & 15, kh = lane >> 4;
        int rn = lane & 7, knh = (lane >> 3) & 1;
#pragma unroll
        for (int kk = 0; kk < 2; kk++) {
            uint32_t af[4][4];
#pragma unroll
            for (int mf = 0; mf < 4; mf++) {
                uint32_t ad = su32(&sA[st][(wm * 64 + mf * 16 + r16) * ASTR + kk * 16 + kh * 8]);
                asm volatile("ldmatrix.sync.aligned.m8n8.x4.shared.b16 {%0,%1,%2,%3}, [%4];"
                    : "=r"(af[mf][0]), "=r"(af[mf][1]), "=r"(af[mf][2]), "=r"(af[mf][3]) : "r"(ad));
            }
            uint32_t bfr[4][2];
#pragma unroll
            for (int nf = 0; nf < 4; nf++) {
                uint32_t bd = su32(&sB[st][(wn * 32 + nf * 8 + rn) * ASTR + kk * 16 + knh * 8]);
                asm volatile("ldmatrix.sync.aligned.m8n8.x2.shared.b16 {%0,%1}, [%2];"
                    : "=r"(bfr[nf][0]), "=r"(bfr[nf][1]) : "r"(bd));
            }
#pragma unroll
            for (int mf = 0; mf < 4; mf++)
#pragma unroll
                for (int nf = 0; nf < 4; nf++) {
                    asm volatile(
                        "mma.sync.aligned.m16n8k16.row.col.f32.bf16.bf16.f32 "
                        "{%0,%1,%2,%3}, {%4,%5,%6,%7}, {%8,%9}, {%0,%1,%2,%3};"
                        : "+f"(cr[mf][nf][0]), "+f"(cr[mf][nf][1]),
                          "+f"(cr[mf][nf][2]), "+f"(cr[mf][nf][3])
                        : "r"(af[mf][0]), "r"(af[mf][1]), "r"(af[mf][2]), "r"(af[mf][3]),
                          "r"(bfr[nf][0]), "r"(bfr[nf][1]));
                }
        }
        __syncthreads();
    }

    // epilogue
    int rr = lane >> 2, cq = (lane & 3) * 2;
#pragma unroll
    for (int mf = 0; mf < 4; mf++) {
#pragma unroll
        for (int nf = 0; nf < 4; nf++) {
            int row0 = rowBase + wm * 64 + mf * 16 + rr;
            int col = colBase + wn * 32 + nf * 8 + cq;
            if (row0 < Meff)
                *(float2*)&C[(size_t)row0 * N + col] =
                    make_float2(cr[mf][nf][0], cr[mf][nf][1]);
            if (row0 + 8 < Meff)
                *(float2*)&C[(size_t)(row0 + 8) * N + col] =
                    make_float2(cr[mf][nf][2], cr[mf][nf][3]);
        }
    }
}

// ---------------- weight transpose + convert: W[K,N] f32 -> Wt[N,K] bf16 -
__global__ void wconv_kernel(const float* __restrict__ W, __nv_bfloat16* __restrict__ Wt,
                             int K, int N) {
    __shared__ float t[32][33];
    const float* Wz = W + (size_t)blockIdx.z * K * N;
    __nv_bfloat16* Wtz = Wt + (size_t)blockIdx.z * K * N;
    int n0 = blockIdx.x * 32, k0 = blockIdx.y * 32;
    int tx = threadIdx.x, ty = threadIdx.y;
#pragma unroll
    for (int r = 0; r < 32; r += 8)
        t[ty + r][tx] = Wz[(size_t)(k0 + ty + r) * N + n0 + tx];
    __syncthreads();
#pragma unroll
    for (int r = 0; r < 32; r += 8)
        Wtz[(size_t)(n0 + ty + r) * K + k0 + tx] = __float2bfloat16(t[tx][ty + r]);
}

// ---------------- RMSNorm (dual output: f32 optional + bf16) -------------
__global__ void rmsnorm_kernel(const float* __restrict__ x,
                               const float* __restrict__ w,
                               float* __restrict__ of,
                               __nv_bfloat16* __restrict__ ob) {
    int row = blockIdx.x;
    int tid = threadIdx.x;
    const float* xr = x + (size_t)row * CC;
    float s = 0.f;
    for (int i = tid; i < CC; i += 256) { float v = xr[i]; s += v * v; }
    __shared__ float red[256];
    red[tid] = s; __syncthreads();
    for (int o2 = 128; o2 > 0; o2 >>= 1) {
        if (tid < o2) red[tid] += red[tid + o2];
        __syncthreads();
    }
    float scale = rsqrtf(red[0] / (float)CC + 1e-6f);
    for (int i = tid; i < CC; i += 256) {
        float v = xr[i] * scale * w[i];
        if (of) of[(size_t)row * CC + i] = v;
        ob[(size_t)row * CC + i] = __float2bfloat16(v);
    }
}

// ---------------- RoPE (in place), X: [NTOK, nheads*64] ----------------
__global__ void rope_kernel(float* __restrict__ X, int nheads) {
    int i = blockIdx.x * blockDim.x + threadIdx.x;
    int total = NTOK * nheads * 32;
    if (i >= total) return;
    int p = i & 31;
    int tmp = i >> 5;
    int hh = tmp % nheads;
    int row = tmp / nheads;
    int t = row % TT;
    float invf = expf(-(float)p * (logf(10000.f) / 32.f));
    float ang = (float)t * invf;
    float cs = cosf(ang), sn = sinf(ang);
    size_t base = (size_t)row * (nheads * 64) + hh * 64;
    float a = X[base + p];
    float b = X[base + p + 32];
    X[base + p]      = a * cs - b * sn;
    X[base + p + 32] = b * cs + a * sn;
}

// ---------------- flash attention, sliding window (fp32, bf16 out) ------
__global__ void attn_kernel(const float* __restrict__ Q,
                            const float* __restrict__ Kk,
                            const float* __restrict__ V,
                            __nv_bfloat16* __restrict__ O) {
    int qb = blockIdx.x, h = blockIdx.y, b = blockIdx.z;
    int t = qb * 64 + threadIdx.x;
    int kvh = h / NREP;
    const float* qrow = Q + ((size_t)(b * TT + t)) * CC + h * DH;
    float q[DH];
#pragma unroll
    for (int d = 0; d < DH; d++) q[d] = qrow[d] * 0.125f;
    float acc[DH];
#pragma unroll
    for (int d = 0; d < DH; d++) acc[d] = 0.f;
    float m = -1e30f, l = 0.f;

    int kstart = qb * 64 - WIN; if (kstart < 0) kstart = 0;
    __shared__ float Ks[64][65];
    __shared__ float Vs[64][65];

    for (int k0 = kstart; k0 <= qb * 64; k0 += 64) {
        __syncthreads();
        for (int r = 0; r < 64; r++) {
            size_t kr = ((size_t)(b * TT + k0 + r)) * (KVH * DH) + kvh * DH;
            Ks[r][threadIdx.x] = Kk[kr + threadIdx.x];
            Vs[r][threadIdx.x] = V[kr + threadIdx.x];
        }
        __syncthreads();
        for (int j = 0; j < 64; j++) {
            int kg = k0 + j;
            if (kg > t || kg < t - WIN) continue;
            float s = 0.f;
#pragma unroll
            for (int d = 0; d < DH; d++) s += q[d] * Ks[j][d];
            float p;
            if (s > m) {
                float corr = __expf(m - s);
                l *= corr;
#pragma unroll
                for (int d = 0; d < DH; d++) acc[d] *= corr;
                m = s; p = 1.f;
            } else {
                p = __expf(s - m);
            }
            l += p;
#pragma unroll
            for (int d = 0; d < DH; d++) acc[d] += p * Vs[j][d];
        }
    }
    float inv = 1.f / l;
    __nv_bfloat16* orow = O + ((size_t)(b * TT + t)) * CC + h * DH;
#pragma unroll
    for (int d = 0; d < DH; d++) orow[d] = __float2bfloat16(acc[d] * inv);
}

// ---------------- residual add ----------------
__global__ void resadd_kernel(const float* __restrict__ x,
                              const float* __restrict__ y,
                              const float* __restrict__ alpha,
                              float* __restrict__ o) {
    int i = blockIdx.x * blockDim.x + threadIdx.x;
    if (i >= OUT_MAIN) return;
    o[i] = x[i] + (*alpha) * y[i];
}

// ---------------- router ----------------
__global__ void route_kernel(const float* __restrict__ xf,
                             const float* __restrict__ gw) {
    int warp = threadIdx.x >> 5, lane = threadIdx.x & 31;
    int tok = blockIdx.x * 4 + warp;
    if (tok >= NTOK) return;
    const float* xr = xf + (size_t)tok * CC;
    float part[EE];
#pragma unroll
    for (int e = 0; e < EE; e++) part[e] = 0.f;
    for (int d = lane; d < CC; d += 32) {
        float xv = xr[d];
#pragma unroll
        for (int e = 0; e < EE; e++) part[e] += xv * gw[d * EE + e];
    }
#pragma unroll
    for (int e = 0; e < EE; e++)
#pragma unroll
        for (int o = 16; o > 0; o >>= 1)
            part[e] += __shfl_xor_sync(0xffffffffu, part[e], o);
    if (lane == 0) {
        float v0 = -1e30f; int i0 = 0;
#pragma unroll
        for (int e = 0; e < EE; e++) if (part[e] > v0) { v0 = part[e]; i0 = e; }
        float v1 = -1e30f; int i1 = 0;
#pragma unroll
        for (int e = 0; e < EE; e++)
            if (e != i0 && part[e] > v1) { v1 = part[e]; i1 = e; }
        float ex = expf(v1 - v0);
        float w0 = 1.f / (1.f + ex);
        float w1 = ex / (1.f + ex);
        g_sel[tok * 2] = i0; g_sel[tok * 2 + 1] = i1;
        g_selw[tok * 2] = w0; g_selw[tok * 2 + 1] = w1;
        float mx = v0, sum = 0.f, pe[EE];
#pragma unroll
        for (int e = 0; e < EE; e++) { pe[e] = expf(part[e] - mx); sum += pe[e]; }
#pragma unroll
        for (int e = 0; e < EE; e++) g_probs[tok * EE + e] = pe[e] / sum;
        float lse = mx + logf(sum);
        g_lse2[tok] = lse * lse;
    }
}

// ---------------- aux loss ----------------
__global__ void aux_kernel() {
    __shared__ float red[256];
    int tid = threadIdx.x;
    float loadv[EE];
#pragma unroll
    for (int e = 0; e < EE; e++) loadv[e] = 0.f;
    for (int n = tid; n < NTOK; n += 256) {
#pragma unroll
        for (int e = 0; e < EE; e++) loadv[e] += g_probs[n * EE + e];
    }
    float loads[EE];
    for (int e = 0; e < EE; e++) {
        red[tid] = loadv[e]; __syncthreads();
        for (int o = 128; o > 0; o >>= 1) {
            if (tid < o) red[tid] += red[tid + o];
            __syncthreads();
        }
        loads[e] = red[0]; __syncthreads();
    }
    float zp = 0.f;
    for (int n = tid; n < NTOK; n += 256) zp += g_lse2[n];
    red[tid] = zp; __syncthreads();
    for (int o = 128; o > 0; o >>= 1) {
        if (tid < o) red[tid] += red[tid + o];
        __syncthreads();
    }
    if (tid == 0) {
        float tot = 0.f;
        for (int e = 0; e < EE; e++) tot += loads[e];
        float lb = 0.f;
        for (int e = 0; e < EE; e++) { float f = loads[e] / tot; lb += f * f; }
        lb *= (float)EE;
        float z = red[0] / (float)NTOK;
        g_aux = 0.01f * lb + 0.001f * z;
    }
}

__global__ void zero_cnt_kernel() { if (threadIdx.x < EE) g_cnt[threadIdx.x] = 0; }

__global__ void assign_kernel() {
    int i = blockIdx.x * blockDim.x + threadIdx.x;
    if (i >= NTOK) return;
#pragma unroll
    for (int kk = 0; kk < TOPK; kk++) {
        int e = g_sel[i * 2 + kk];
        int pos = atomicAdd(&g_cnt[e], 1);
        g_idx[e * NTOK + pos] = i;
        g_w[e * NTOK + pos] = g_selw[i * 2 + kk];
    }
}

__global__ void gather_kernel(__nv_bfloat16* __restrict__ dst,
                              const __nv_bfloat16* __restrict__ src,
                              const int* __restrict__ idx, const int* __restrict__ cnt) {
    int b = blockIdx.x;
    if (b >= *cnt) return;
    int t = idx[b];
    uint4* d4 = (uint4*)(dst + (size_t)b * CC);
    const uint4* s4 = (const uint4*)(src + (size_t)t * CC);
    int i = threadIdx.x;
    if (i < CC * 2 / 16) d4[i] = s4[i];
}

__global__ void silu_mul_kernel(const float* __restrict__ a, const float* __restrict__ b,
                                __nv_bfloat16* __restrict__ o,
                                int M, const int* mPtr) {
    long total = (long)(mPtr ? *mPtr : M) * FF;
    long i = (long)blockIdx.x * blockDim.x + threadIdx.x;
    if (i >= total) return;
    float v = a[i];
    float s = v / (1.f + __expf(-v));
    o[i] = __float2bfloat16(s * b[i]);
}

__global__ void scatter_kernel(float* __restrict__ dst, const float* __restrict__ src,
                               const int* __restrict__ idx, const float* __restrict__ wl,
                               const int* __restrict__ cnt) {
    int b = blockIdx.x;
    if (b >= *cnt) return;
    int t = idx[b];
    float w = wl[b];
    for (int i = threadIdx.x; i < CC; i += blockDim.x)
        dst[(size_t)t * CC + i] += w * src[(size_t)b * CC + i];
}

__global__ void final_kernel(const float* __restrict__ h, const float* __restrict__ moe,
                             const float* __restrict__ alpha, float* __restrict__ out) {
    int i = blockIdx.x * blockDim.x + threadIdx.x;
    if (i >= OUT_MAIN) return;
    out[i] = h[i] + (*alpha) * moe[i];
}

__global__ void auxwrite_kernel(float* __restrict__ out) { out[OUT_MAIN] = g_aux; }

// ---------------- launch ----------------
extern "C" void kernel_launch(void* const* d_in, const int* in_sizes, int n_in,
                              void* d_out, int out_size) {
    const float* x      = (const float*)d_in[0];
    const float* ln1    = (const float*)d_in[1];
    const float* ln2    = (const float*)d_in[2];
    const float* wq     = (const float*)d_in[3];
    const float* wk     = (const float*)d_in[4];
    const float* wv     = (const float*)d_in[5];
    const float* wo     = (const float*)d_in[6];
    const float* sw1    = (const float*)d_in[7];
    const float* sw2    = (const float*)d_in[8];
    const float* sw3    = (const float*)d_in[9];
    const float* ew1    = (const float*)d_in[10];
    const float* ew2    = (const float*)d_in[11];
    const float* ew3    = (const float*)d_in[12];
    const float* gatew  = (const float*)d_in[13];
    const float* a_attn = (const float*)d_in[14];
    const float* a_moe  = (const float*)d_in[15];
    float* out = (float*)d_out;

    void* p;
    float *q, *k, *v, *proj, *h, *xf, *moe, *g1, *g2, *eo, *wlst;
    int *cnt, *idxl;
    __nv_bfloat16 *xnb, *aob, *xfb, *xgb, *g1b;
    __nv_bfloat16 *wqt, *wkt, *wvt, *wot, *sw1t, *sw2t, *sw3t, *ew1t, *ew2t, *ew3t;
    cudaGetSymbolAddress(&p, g_q);    q    = (float*)p;
    cudaGetSymbolAddress(&p, g_k);    k    = (float*)p;
    cudaGetSymbolAddress(&p, g_v);    v    = (float*)p;
    cudaGetSymbolAddress(&p, g_proj); proj = (float*)p;
    cudaGetSymbolAddress(&p, g_h);    h    = (float*)p;
    cudaGetSymbolAddress(&p, g_xf);   xf   = (float*)p;
    cudaGetSymbolAddress(&p, g_moe);  moe  = (float*)p;
    cudaGetSymbolAddress(&p, g_g1);   g1   = (float*)p;
    cudaGetSymbolAddress(&p, g_g2);   g2   = (float*)p;
    cudaGetSymbolAddress(&p, g_eo);   eo   = (float*)p;
    cudaGetSymbolAddress(&p, g_cnt);  cnt  = (int*)p;
    cudaGetSymbolAddress(&p, g_idx);  idxl = (int*)p;
    cudaGetSymbolAddress(&p, g_w);    wlst = (float*)p;
    cudaGetSymbolAddress(&p, g_xnb);  xnb  = (__nv_bfloat16*)p;
    cudaGetSymbolAddress(&p, g_aob);  aob  = (__nv_bfloat16*)p;
    cudaGetSymbolAddress(&p, g_xfb);  xfb  = (__nv_bfloat16*)p;
    cudaGetSymbolAddress(&p, g_xgb);  xgb  = (__nv_bfloat16*)p;
    cudaGetSymbolAddress(&p, g_g1b);  g1b  = (__nv_bfloat16*)p;
    cudaGetSymbolAddress(&p, g_wqt);  wqt  = (__nv_bfloat16*)p;
    cudaGetSymbolAddress(&p, g_wkt);  wkt  = (__nv_bfloat16*)p;
    cudaGetSymbolAddress(&p, g_wvt);  wvt  = (__nv_bfloat16*)p;
    cudaGetSymbolAddress(&p, g_wot);  wot  = (__nv_bfloat16*)p;
    cudaGetSymbolAddress(&p, g_sw1t); sw1t = (__nv_bfloat16*)p;
    cudaGetSymbolAddress(&p, g_sw2t); sw2t = (__nv_bfloat16*)p;
    cudaGetSymbolAddress(&p, g_sw3t); sw3t = (__nv_bfloat16*)p;
    cudaGetSymbolAddress(&p, g_ew1t); ew1t = (__nv_bfloat16*)p;
    cudaGetSymbolAddress(&p, g_ew2t); ew2t = (__nv_bfloat16*)p;
    cudaGetSymbolAddress(&p, g_ew3t); ew3t = (__nv_bfloat16*)p;

    dim3 cb(32, 8);
    // weight conversion (transpose + bf16)
    wconv_kernel<<<dim3(CC/32,  CC/32, 1), cb>>>(wq,  wqt,  CC, CC);
    wconv_kernel<<<dim3(KVH*DH/32, CC/32, 1), cb>>>(wk,  wkt,  CC, KVH*DH);
    wconv_kernel<<<dim3(KVH*DH/32, CC/32, 1), cb>>>(wv,  wvt,  CC, KVH*DH);
    wconv_kernel<<<dim3(CC/32,  CC/32, 1), cb>>>(wo,  wot,  CC, CC);
    wconv_kernel<<<dim3(FF/32,  CC/32, 1), cb>>>(sw1, sw1t, CC, FF);
    wconv_kernel<<<dim3(FF/32,  CC/32, 1), cb>>>(sw2, sw2t, CC, FF);
    wconv_kernel<<<dim3(CC/32,  FF/32, 1), cb>>>(sw3, sw3t, FF, CC);
    wconv_kernel<<<dim3(FF/32,  CC/32, EE), cb>>>(ew1, ew1t, CC, FF);
    wconv_kernel<<<dim3(FF/32,  CC/32, EE), cb>>>(ew2, ew2t, CC, FF);
    wconv_kernel<<<dim3(CC/32,  FF/32, EE), cb>>>(ew3, ew3t, FF, CC);

    // 1) pre-attn norm (bf16 only)
    rmsnorm_kernel<<<NTOK, 256>>>(x, ln1, nullptr, xnb);
    // 2) QKV projections (tensor core)
    gemm_mma<<<dim3(CC/128, NTOK/128), 256>>>(xnb, wqt, q, NTOK, CC, CC, nullptr);
    gemm_mma<<<dim3(KVH*DH/128, NTOK/128), 256>>>(xnb, wkt, k, NTOK, KVH*DH, CC, nullptr);
    gemm_mma<<<dim3(KVH*DH/128, NTOK/128), 256>>>(xnb, wvt, v, NTOK, KVH*DH, CC, nullptr);
    // 3) RoPE
    rope_kernel<<<(NTOK * HH * 32 + 255) / 256, 256>>>(q, HH);
    rope_kernel<<<(NTOK * KVH * 32 + 255) / 256, 256>>>(k, KVH);
    // 4) attention (fp32, bf16 out)
    attn_kernel<<<dim3(TT/64, HH, BB), 64>>>(q, k, v, aob);
    // 5) output projection + ReZero residual
    gemm_mma<<<dim3(CC/128, NTOK/128), 256>>>(aob, wot, proj, NTOK, CC, CC, nullptr);
    resadd_kernel<<<(OUT_MAIN + 255) / 256, 256>>>(x, proj, a_attn, h);
    // 6) post-attn norm (f32 + bf16)
    rmsnorm_kernel<<<NTOK, 256>>>(h, ln2, xf, xfb);
    // 7) routing + aux
    route_kernel<<<NTOK / 4, 128>>>(xf, gatew);
    aux_kernel<<<1, 256>>>();
    zero_cnt_kernel<<<1, 32>>>();
    assign_kernel<<<(NTOK + 255) / 256, 256>>>();
    // 8) shared expert SwiGLU
    gemm_mma<<<dim3(FF/128, NTOK/128), 256>>>(xfb, sw1t, g1, NTOK, FF, CC, nullptr);
    gemm_mma<<<dim3(FF/128, NTOK/128), 256>>>(xfb, sw2t, g2, NTOK, FF, CC, nullptr);
    silu_mul_kernel<<<(int)((NTOK * (long)FF + 255) / 256), 256>>>(g1, g2, g1b, NTOK, nullptr);
    gemm_mma<<<dim3(CC/128, NTOK/128), 256>>>(g1b, sw3t, moe, NTOK, CC, FF, nullptr);
    // 9) routed experts, sparse
    for (int e = 0; e < EE; e++) {
        const int* ce = cnt + e;
        const int* ie = idxl + e * NTOK;
        const float* we = wlst + e * NTOK;
        gather_kernel<<<NTOK, 128>>>(xgb, xfb, ie, ce);
        gemm_mma<<<dim3(FF/128, NTOK/128), 256>>>(xgb, ew1t + (size_t)e * CC * FF, g1, NTOK, FF, CC, ce);
        gemm_mma<<<dim3(FF/128, NTOK/128), 256>>>(xgb, ew2t + (size_t)e * CC * FF, g2, NTOK, FF, CC, ce);
        silu_mul_kernel<<<(int)((NTOK * (long)FF + 255) / 256), 256>>>(g1, g2, g1b, 0, ce);
        gemm_mma<<<dim3(CC/128, NTOK/128), 256>>>(g1b, ew3t + (size_t)e * FF * CC, eo, NTOK, CC, FF, ce);
        scatter_kernel<<<NTOK, 256>>>(moe, eo, ie, we, ce);
    }
    // 10) final ReZero residual + aux scalar
    final_kernel<<<(OUT_MAIN + 255) / 256, 256>>>(h, moe, a_moe, out);
    if (out_size > OUT_MAIN) auxwrite_kernel<<<1, 1>>>(out);
}

// round 5
// speedup vs baseline: 1.2600x; 1.2600x over previous
#include <cuda_runtime.h>
#include <cuda_bf16.h>
#include <math.h>
#include <stdint.h>

// Problem constants
#define BB   2
#define TT   2048
#define CC   1024
#define HH   16
#define KVH  4
#define DH   64
#define NREP 4
#define FF   4096
#define EE   8
#define TOPK 2
#define WIN  1024
#define NTOK (BB*TT)            // 4096
#define OUT_MAIN (NTOK*CC)      // 4194304
#define QKVN (CC + 2*KVH*DH)    // 1536
#define ECAP 9216               // 8192 real rows + 8*127 padding, 128-aligned

// ---------------- scratch (device globals; no allocation) ----------------
__device__ float g_qkv [NTOK*QKVN];
__device__ float g_proj[NTOK*CC];
__device__ float g_h   [NTOK*CC];
__device__ float g_xf  [NTOK*CC];
__device__ float g_moe [NTOK*CC];
__device__ float g_g12 [(size_t)ECAP*2*FF];
__device__ float g_eo  [(size_t)ECAP*CC];
__device__ float g_probs[NTOK*EE];
__device__ float g_lse2[NTOK];
__device__ int   g_sel [NTOK*2];
__device__ float g_selw[NTOK*2];
__device__ int   g_cnt [EE];
__device__ int   g_cnt2[EE];
__device__ int   g_off [EE+1];
__device__ int   g_idx [ECAP];
__device__ int   g_tokrow[NTOK*2];
__device__ float g_aux;

// bf16 activations
__device__ __nv_bfloat16 g_xnb [NTOK*CC];
__device__ __nv_bfloat16 g_aob [NTOK*CC];
__device__ __nv_bfloat16 g_xfb [NTOK*CC];
__device__ __nv_bfloat16 g_xgb [(size_t)ECAP*CC];
__device__ __nv_bfloat16 g_g1b [(size_t)ECAP*FF];

// bf16 transposed weights [N,K]
__device__ __nv_bfloat16 g_wqkvt[QKVN*CC];
__device__ __nv_bfloat16 g_wot  [CC*CC];
__device__ __nv_bfloat16 g_sw12t[2*FF*CC];
__device__ __nv_bfloat16 g_sw3t [CC*FF];
__device__ __nv_bfloat16 g_ew12t[(size_t)EE*2*FF*CC];
__device__ __nv_bfloat16 g_ew3t [(size_t)EE*CC*FF];

__device__ __forceinline__ uint32_t su32(const void* p) {
    uint32_t a;
    asm("{ .reg .u64 t; cvta.to.shared.u64 t, %1; cvt.u32.u64 %0, t; }" : "=r"(a) : "l"(p));
    return a;
}

#define CP_ASYNC16(d, s) asm volatile("cp.async.cg.shared.global [%0], [%1], 16;" :: "r"(d), "l"(s))
#define CP_COMMIT()      asm volatile("cp.async.commit_group;" ::: "memory")
#define CP_WAIT(n)       asm volatile("cp.async.wait_group %0;" :: "n"(n) : "memory")

#define BM 128
#define BN 128
#define BK 32
#define ASTR 40   // padded row stride in bf16 elems

// ================= shared mainloop body (macro to reuse) ==================
// computes 128x128 tile at (rowBase, colBase) from A [stride K] and Bt [N,K]
#define GEMM_BODY(A_, Bt_, C_, N_, K_, STORE_GUARD)                            \
    __shared__ __align__(16) __nv_bfloat16 sA[2][BM * ASTR];                   \
    __shared__ __align__(16) __nv_bfloat16 sB[2][BM * ASTR];                   \
    int tid = threadIdx.x;                                                     \
    int wid = tid >> 5, lane = tid & 31;                                       \
    int wm = wid >> 2, wn = wid & 3;                                           \
    float cr[4][4][4];                                                         \
    _Pragma("unroll") for (int i = 0; i < 4; i++)                              \
    _Pragma("unroll") for (int j = 0; j < 4; j++)                              \
    _Pragma("unroll") for (int r = 0; r < 4; r++) cr[i][j][r] = 0.f;           \
    int lrow = tid >> 1;                                                       \
    int lc16 = (tid & 1) * 16;                                                 \
    int nCh = (K_) / BK;                                                       \
    {                                                                          \
        const __nv_bfloat16* srcA0 = (A_) + (size_t)(rowBase + lrow) * (K_) + lc16; \
        const __nv_bfloat16* srcB0 = (Bt_) + (size_t)(colBase + lrow) * (K_) + lc16; \
        uint32_t dA0 = su32(&sA[0][lrow * ASTR + lc16]);                       \
        uint32_t dB0 = su32(&sB[0][lrow * ASTR + lc16]);                       \
        CP_ASYNC16(dA0, srcA0); CP_ASYNC16(dA0 + 16, srcA0 + 8);               \
        CP_ASYNC16(dB0, srcB0); CP_ASYNC16(dB0 + 16, srcB0 + 8);               \
        CP_COMMIT();                                                           \
    }                                                                          \
    for (int ch = 0; ch < nCh; ch++) {                                         \
        int st = ch & 1;                                                       \
        if (ch + 1 < nCh) {                                                    \
            int k0 = (ch + 1) * BK;                                            \
            const __nv_bfloat16* srcA = (A_) + (size_t)(rowBase + lrow) * (K_) + k0 + lc16; \
            const __nv_bfloat16* srcB = (Bt_) + (size_t)(colBase + lrow) * (K_) + k0 + lc16; \
            uint32_t dA = su32(&sA[st ^ 1][lrow * ASTR + lc16]);               \
            uint32_t dB = su32(&sB[st ^ 1][lrow * ASTR + lc16]);               \
            CP_ASYNC16(dA, srcA); CP_ASYNC16(dA + 16, srcA + 8);               \
            CP_ASYNC16(dB, srcB); CP_ASYNC16(dB + 16, srcB + 8);               \
            CP_COMMIT(); CP_WAIT(1);                                           \
        } else { CP_WAIT(0); }                                                 \
        __syncthreads();                                                       \
        int r16 = lane & 15, kh = lane >> 4;                                   \
        int rn = lane & 7, knh = (lane >> 3) & 1;                              \
        _Pragma("unroll") for (int kk = 0; kk < 2; kk++) {                     \
            uint32_t af[4][4];                                                 \
            _Pragma("unroll") for (int mf = 0; mf < 4; mf++) {                 \
                uint32_t ad = su32(&sA[st][(wm * 64 + mf * 16 + r16) * ASTR + kk * 16 + kh * 8]); \
                asm volatile("ldmatrix.sync.aligned.m8n8.x4.shared.b16 {%0,%1,%2,%3}, [%4];" \
                    : "=r"(af[mf][0]), "=r"(af[mf][1]), "=r"(af[mf][2]), "=r"(af[mf][3]) : "r"(ad)); \
            }                                                                  \
            uint32_t bfr[4][2];                                                \
            _Pragma("unroll") for (int nf = 0; nf < 4; nf++) {                 \
                uint32_t bd = su32(&sB[st][(wn * 32 + nf * 8 + rn) * ASTR + kk * 16 + knh * 8]); \
                asm volatile("ldmatrix.sync.aligned.m8n8.x2.shared.b16 {%0,%1}, [%2];" \
                    : "=r"(bfr[nf][0]), "=r"(bfr[nf][1]) : "r"(bd));           \
            }                                                                  \
            _Pragma("unroll") for (int mf = 0; mf < 4; mf++)                   \
            _Pragma("unroll") for (int nf = 0; nf < 4; nf++) {                 \
                asm volatile(                                                  \
                    "mma.sync.aligned.m16n8k16.row.col.f32.bf16.bf16.f32 "     \
                    "{%0,%1,%2,%3}, {%4,%5,%6,%7}, {%8,%9}, {%0,%1,%2,%3};"    \
                    : "+f"(cr[mf][nf][0]), "+f"(cr[mf][nf][1]),                \
                      "+f"(cr[mf][nf][2]), "+f"(cr[mf][nf][3])                 \
                    : "r"(af[mf][0]), "r"(af[mf][1]), "r"(af[mf][2]), "r"(af[mf][3]), \
                      "r"(bfr[nf][0]), "r"(bfr[nf][1]));                       \
            }                                                                  \
        }                                                                      \
        __syncthreads();                                                       \
    }                                                                          \
    int rr = lane >> 2, cq = (lane & 3) * 2;                                   \
    _Pragma("unroll") for (int mf = 0; mf < 4; mf++) {                         \
        _Pragma("unroll") for (int nf = 0; nf < 4; nf++) {                     \
            int row0 = rowBase + wm * 64 + mf * 16 + rr;                       \
            int col = colBase + wn * 32 + nf * 8 + cq;                         \
            if (STORE_GUARD)                                                   \
                *(float2*)&(C_)[(size_t)row0 * (N_) + col] =                   \
                    make_float2(cr[mf][nf][0], cr[mf][nf][1]);                 \
            if (STORE_GUARD2)                                                  \
                *(float2*)&(C_)[(size_t)(row0 + 8) * (N_) + col] =             \
                    make_float2(cr[mf][nf][2], cr[mf][nf][3]);                 \
        }                                                                      \
    }

// ================= dense GEMM =================
__global__ __launch_bounds__(256) void gemm_mma(
    const __nv_bfloat16* __restrict__ A, const __nv_bfloat16* __restrict__ Bt,
    float* __restrict__ C, int M, int N, int K)
{
    int rowBase = blockIdx.y * BM;
    int colBase = blockIdx.x * BN;
#define STORE_GUARD2 (true)
    GEMM_BODY(A, Bt, C, N, K, true)
#undef STORE_GUARD2
}

// ================= batched MoE GEMM: expert picked per row-block =========
__global__ __launch_bounds__(256) void gemm_moe(
    const __nv_bfloat16* __restrict__ A, const __nv_bfloat16* __restrict__ Wb,
    float* __restrict__ C, int N, int K, long wstride)
{
    int total = g_off[EE];
    int rowBase = blockIdx.y * BM;
    if (rowBase >= total) return;
    int colBase = blockIdx.x * BN;
    int e = 0;
    while (g_off[e + 1] <= rowBase) e++;
    const __nv_bfloat16* Bt = Wb + (size_t)e * wstride;
#define STORE_GUARD2 (true)
    GEMM_BODY(A, Bt, C, N, K, true)
#undef STORE_GUARD2
}

// ---------------- fast weight transpose+convert -------------------------
// W[K,N] f32 -> Wt[N,K] bf16. 64x64 tiles, vectorized both phases.
__global__ void wconv2(const float* __restrict__ W, __nv_bfloat16* __restrict__ Wt,
                       int K, int N, long sstride, long dstride) {
    __shared__ float t[64][65];
    const float* Wz = W + (size_t)blockIdx.z * sstride;
    __nv_bfloat16* Wtz = Wt + (size_t)blockIdx.z * dstride;
    int n0 = blockIdx.x * 64, k0 = blockIdx.y * 64;
    int tid = threadIdx.x;
    int rr = tid >> 4;
    int c4 = (tid & 15) * 4;
#pragma unroll
    for (int r = 0; r < 64; r += 16) {
        float4 v = *(const float4*)&Wz[(size_t)(k0 + r + rr) * N + n0 + c4];
        t[r + rr][c4 + 0] = v.x; t[r + rr][c4 + 1] = v.y;
        t[r + rr][c4 + 2] = v.z; t[r + rr][c4 + 3] = v.w;
    }
    __syncthreads();
    int nl = tid >> 3;
    int c8 = (tid & 7) * 8;
#pragma unroll
    for (int r = 0; r < 64; r += 32) {
        int n = nl + r;
        __nv_bfloat16 o[8];
#pragma unroll
        for (int j = 0; j < 8; j++) o[j] = __float2bfloat16(t[c8 + j][n]);
        *(uint4*)&Wtz[(size_t)(n0 + n) * K + k0 + c8] = *(uint4*)o;
    }
}

// ---------------- RMSNorm (dual output: f32 optional + bf16) -------------
__global__ void rmsnorm_kernel(const float* __restrict__ x,
                               const float* __restrict__ w,
                               float* __restrict__ of,
                               __nv_bfloat16* __restrict__ ob) {
    int row = blockIdx.x;
    int tid = threadIdx.x;
    const float* xr = x + (size_t)row * CC;
    float s = 0.f;
    for (int i = tid; i < CC; i += 256) { float v = xr[i]; s += v * v; }
    __shared__ float red[256];
    red[tid] = s; __syncthreads();
    for (int o2 = 128; o2 > 0; o2 >>= 1) {
        if (tid < o2) red[tid] += red[tid + o2];
        __syncthreads();
    }
    float scale = rsqrtf(red[0] / (float)CC + 1e-6f);
    for (int i = tid; i < CC; i += 256) {
        float v = xr[i] * scale * w[i];
        if (of) of[(size_t)row * CC + i] = v;
        ob[(size_t)row * CC + i] = __float2bfloat16(v);
    }
}

// ---------------- RoPE (in place), X row stride QKVN ---------------------
__global__ void rope_kernel(float* __restrict__ X, int nheads, int hoff) {
    int i = blockIdx.x * blockDim.x + threadIdx.x;
    int total = NTOK * nheads * 32;
    if (i >= total) return;
    int p = i & 31;
    int tmp = i >> 5;
    int hh = tmp % nheads;
    int row = tmp / nheads;
    int t = row % TT;
    float invf = expf(-(float)p * (logf(10000.f) / 32.f));
    float ang = (float)t * invf;
    float cs = cosf(ang), sn = sinf(ang);
    size_t base = (size_t)row * QKVN + hoff + hh * 64;
    float a = X[base + p];
    float b = X[base + p + 32];
    X[base + p]      = a * cs - b * sn;
    X[base + p + 32] = b * cs + a * sn;
}

// ---------------- flash attention, sliding window (fp32, bf16 out) ------
__global__ void attn_kernel(const float* __restrict__ QKV,
                            __nv_bfloat16* __restrict__ O) {
    int qb = blockIdx.x, h = blockIdx.y, b = blockIdx.z;
    int t = qb * 64 + threadIdx.x;
    int kvh = h / NREP;
    const float* qrow = QKV + ((size_t)(b * TT + t)) * QKVN + h * DH;
    float q[DH];
#pragma unroll
    for (int d = 0; d < DH; d++) q[d] = qrow[d] * 0.125f;
    float acc[DH];
#pragma unroll
    for (int d = 0; d < DH; d++) acc[d] = 0.f;
    float m = -1e30f, l = 0.f;

    int kstart = qb * 64 - WIN; if (kstart < 0) kstart = 0;
    __shared__ float Ks[64][65];
    __shared__ float Vs[64][65];

    for (int k0 = kstart; k0 <= qb * 64; k0 += 64) {
        __syncthreads();
        for (int r = 0; r < 64; r++) {
            size_t kr = ((size_t)(b * TT + k0 + r)) * QKVN + kvh * DH;
            Ks[r][threadIdx.x] = QKV[kr + CC + threadIdx.x];
            Vs[r][threadIdx.x] = QKV[kr + CC + KVH * DH + threadIdx.x];
        }
        __syncthreads();
        for (int j = 0; j < 64; j++) {
            int kg = k0 + j;
            if (kg > t || kg < t - WIN) continue;
            float s = 0.f;
#pragma unroll
            for (int d = 0; d < DH; d++) s += q[d] * Ks[j][d];
            float p;
            if (s > m) {
                float corr = __expf(m - s);
                l *= corr;
#pragma unroll
                for (int d = 0; d < DH; d++) acc[d] *= corr;
                m = s; p = 1.f;
            } else {
                p = __expf(s - m);
            }
            l += p;
#pragma unroll
            for (int d = 0; d < DH; d++) acc[d] += p * Vs[j][d];
        }
    }
    float inv = 1.f / l;
    __nv_bfloat16* orow = O + ((size_t)(b * TT + t)) * CC + h * DH;
#pragma unroll
    for (int d = 0; d < DH; d++) orow[d] = __float2bfloat16(acc[d] * inv);
}

// ---------------- residual add ----------------
__global__ void resadd_kernel(const float* __restrict__ x,
                              const float* __restrict__ y,
                              const float* __restrict__ alpha,
                              float* __restrict__ o) {
    int i = blockIdx.x * blockDim.x + threadIdx.x;
    if (i >= OUT_MAIN) return;
    o[i] = x[i] + (*alpha) * y[i];
}

// ---------------- router ----------------
__global__ void route_kernel(const float* __restrict__ xf,
                             const float* __restrict__ gw) {
    int warp = threadIdx.x >> 5, lane = threadIdx.x & 31;
    int tok = blockIdx.x * 4 + warp;
    if (tok >= NTOK) return;
    const float* xr = xf + (size_t)tok * CC;
    float part[EE];
#pragma unroll
    for (int e = 0; e < EE; e++) part[e] = 0.f;
    for (int d = lane; d < CC; d += 32) {
        float xv = xr[d];
#pragma unroll
        for (int e = 0; e < EE; e++) part[e] += xv * gw[d * EE + e];
    }
#pragma unroll
    for (int e = 0; e < EE; e++)
#pragma unroll
        for (int o = 16; o > 0; o >>= 1)
            part[e] += __shfl_xor_sync(0xffffffffu, part[e], o);
    if (lane == 0) {
        float v0 = -1e30f; int i0 = 0;
#pragma unroll
        for (int e = 0; e < EE; e++) if (part[e] > v0) { v0 = part[e]; i0 = e; }
        float v1 = -1e30f; int i1 = 0;
#pragma unroll
        for (int e = 0; e < EE; e++)
            if (e != i0 && part[e] > v1) { v1 = part[e]; i1 = e; }
        float ex = expf(v1 - v0);
        float w0 = 1.f / (1.f + ex);
        float w1 = ex / (1.f + ex);
        g_sel[tok * 2] = i0; g_sel[tok * 2 + 1] = i1;
        g_selw[tok * 2] = w0; g_selw[tok * 2 + 1] = w1;
        float mx = v0, sum = 0.f, pe[EE];
#pragma unroll
        for (int e = 0; e < EE; e++) { pe[e] = expf(part[e] - mx); sum += pe[e]; }
#pragma unroll
        for (int e = 0; e < EE; e++) g_probs[tok * EE + e] = pe[e] / sum;
        float lse = mx + logf(sum);
        g_lse2[tok] = lse * lse;
    }
}

// ---------------- aux loss ----------------
__global__ void aux_kernel() {
    __shared__ float red[256];
    int tid = threadIdx.x;
    float loadv[EE];
#pragma unroll
    for (int e = 0; e < EE; e++) loadv[e] = 0.f;
    for (int n = tid; n < NTOK; n += 256) {
#pragma unroll
        for (int e = 0; e < EE; e++) loadv[e] += g_probs[n * EE + e];
    }
    float loads[EE];
    for (int e = 0; e < EE; e++) {
        red[tid] = loadv[e]; __syncthreads();
        for (int o = 128; o > 0; o >>= 1) {
            if (tid < o) red[tid] += red[tid + o];
            __syncthreads();
        }
        loads[e] = red[0]; __syncthreads();
    }
    float zp = 0.f;
    for (int n = tid; n < NTOK; n += 256) zp += g_lse2[n];
    red[tid] = zp; __syncthreads();
    for (int o = 128; o > 0; o >>= 1) {
        if (tid < o) red[tid] += red[tid + o];
        __syncthreads();
    }
    if (tid == 0) {
        float tot = 0.f;
        for (int e = 0; e < EE; e++) tot += loads[e];
        float lb = 0.f;
        for (int e = 0; e < EE; e++) { float f = loads[e] / tot; lb += f * f; }
        lb *= (float)EE;
        float z = red[0] / (float)NTOK;
        g_aux = 0.01f * lb + 0.001f * z;
    }
}

__global__ void zero_cnt_kernel() { if (threadIdx.x < EE) g_cnt[threadIdx.x] = 0; }

__global__ void count_kernel() {
    int i = blockIdx.x * blockDim.x + threadIdx.x;
    if (i >= NTOK) return;
#pragma unroll
    for (int kk = 0; kk < TOPK; kk++)
        atomicAdd(&g_cnt[g_sel[i * 2 + kk]], 1);
}

__global__ void offsets_kernel() {
    if (threadIdx.x == 0) {
        int acc = 0;
        for (int e = 0; e < EE; e++) {
            g_off[e] = acc;
            acc += (g_cnt[e] + BM - 1) & ~(BM - 1);
            g_cnt2[e] = 0;
        }
        g_off[EE] = acc;
    }
}

__global__ void assign_kernel() {
    int i = blockIdx.x * blockDim.x + threadIdx.x;
    if (i >= NTOK) return;
#pragma unroll
    for (int kk = 0; kk < TOPK; kk++) {
        int e = g_sel[i * 2 + kk];
        int pos = atomicAdd(&g_cnt2[e], 1);
        int row = g_off[e] + pos;
        g_idx[row] = i;
        g_tokrow[i * 2 + kk] = row;
    }
}

__global__ void gather_all_kernel(__nv_bfloat16* __restrict__ dst,
                                  const __nv_bfloat16* __restrict__ src) {
    int b = blockIdx.x;
    if (b >= g_off[EE]) return;
    int e = 0;
    while (g_off[e + 1] <= b) e++;
    if (b - g_off[e] >= g_cnt[e]) return;   // padding row: leave as-is (never read)
    int t = g_idx[b];
    uint4* d4 = (uint4*)(dst + (size_t)b * CC);
    const uint4* s4 = (const uint4*)(src + (size_t)t * CC);
    int i = threadIdx.x;
    if (i < CC * 2 / 16) d4[i] = s4[i];
}

// silu over fused [M, 2*FF] buffer -> bf16 [M, FF]
__global__ void silu_mul_kernel(const float* __restrict__ g12,
                                __nv_bfloat16* __restrict__ o,
                                int M, const int* mPtr) {
    long total = (long)(mPtr ? *mPtr : M) * FF;
    long i = (long)blockIdx.x * blockDim.x + threadIdx.x;
    if (i >= total) return;
    long row = i / FF, f = i - row * FF;
    float v = g12[row * (2 * FF) + f];
    float s = v / (1.f + __expf(-v));
    o[i] = __float2bfloat16(s * g12[row * (2 * FF) + FF + f]);
}

// final: out = h + a_moe * (shared + w0*eo[r0] + w1*eo[r1]); deterministic
__global__ void final_kernel(const float* __restrict__ h, const float* __restrict__ moe,
                             const float* __restrict__ eo,
                             const float* __restrict__ alpha, float* __restrict__ out) {
    int t = blockIdx.x;
    float w0 = g_selw[t * 2], w1 = g_selw[t * 2 + 1];
    int r0 = g_tokrow[t * 2], r1 = g_tokrow[t * 2 + 1];
    float a = *alpha;
    const float* hr = h + (size_t)t * CC;
    const float* mr = moe + (size_t)t * CC;
    const float* e0 = eo + (size_t)r0 * CC;
    const float* e1 = eo + (size_t)r1 * CC;
    float* orow = out + (size_t)t * CC;
    for (int i = threadIdx.x; i < CC; i += blockDim.x)
        orow[i] = hr[i] + a * (mr[i] + w0 * e0[i] + w1 * e1[i]);
}

__global__ void auxwrite_kernel(float* __restrict__ out) { out[OUT_MAIN] = g_aux; }

// ---------------- launch ----------------
extern "C" void kernel_launch(void* const* d_in, const int* in_sizes, int n_in,
                              void* d_out, int out_size) {
    const float* x      = (const float*)d_in[0];
    const float* ln1    = (const float*)d_in[1];
    const float* ln2    = (const float*)d_in[2];
    const float* wq     = (const float*)d_in[3];
    const float* wk     = (const float*)d_in[4];
    const float* wv     = (const float*)d_in[5];
    const float* wo     = (const float*)d_in[6];
    const float* sw1    = (const float*)d_in[7];
    const float* sw2    = (const float*)d_in[8];
    const float* sw3    = (const float*)d_in[9];
    const float* ew1    = (const float*)d_in[10];
    const float* ew2    = (const float*)d_in[11];
    const float* ew3    = (const float*)d_in[12];
    const float* gatew  = (const float*)d_in[13];
    const float* a_attn = (const float*)d_in[14];
    const float* a_moe  = (const float*)d_in[15];
    float* out = (float*)d_out;

    void* p;
    float *qkv, *proj, *h, *xf, *moe, *g12, *eo;
    __nv_bfloat16 *xnb, *aob, *xfb, *xgb, *g1b;
    __nv_bfloat16 *wqkvt, *wot, *sw12t, *sw3t, *ew12t, *ew3t;
    cudaGetSymbolAddress(&p, g_qkv);  qkv  = (float*)p;
    cudaGetSymbolAddress(&p, g_proj); proj = (float*)p;
    cudaGetSymbolAddress(&p, g_h);    h    = (float*)p;
    cudaGetSymbolAddress(&p, g_xf);   xf   = (float*)p;
    cudaGetSymbolAddress(&p, g_moe);  moe  = (float*)p;
    cudaGetSymbolAddress(&p, g_g12);  g12  = (float*)p;
    cudaGetSymbolAddress(&p, g_eo);   eo   = (float*)p;
    cudaGetSymbolAddress(&p, g_xnb);  xnb  = (__nv_bfloat16*)p;
    cudaGetSymbolAddress(&p, g_aob);  aob  = (__nv_bfloat16*)p;
    cudaGetSymbolAddress(&p, g_xfb);  xfb  = (__nv_bfloat16*)p;
    cudaGetSymbolAddress(&p, g_xgb);  xgb  = (__nv_bfloat16*)p;
    cudaGetSymbolAddress(&p, g_g1b);  g1b  = (__nv_bfloat16*)p;
    cudaGetSymbolAddress(&p, g_wqkvt); wqkvt = (__nv_bfloat16*)p;
    cudaGetSymbolAddress(&p, g_wot);   wot   = (__nv_bfloat16*)p;
    cudaGetSymbolAddress(&p, g_sw12t); sw12t = (__nv_bfloat16*)p;
    cudaGetSymbolAddress(&p, g_sw3t);  sw3t  = (__nv_bfloat16*)p;
    cudaGetSymbolAddress(&p, g_ew12t); ew12t = (__nv_bfloat16*)p;
    cudaGetSymbolAddress(&p, g_ew3t);  ew3t  = (__nv_bfloat16*)p;

    dim3 cb(256);
    // weight conversion: W[K,N] f32 -> Wt[N,K] bf16 (fused destinations)
    wconv2<<<dim3(CC/64,  CC/64, 1), cb>>>(wq,  wqkvt,                       CC, CC,     0, 0);
    wconv2<<<dim3(KVH*DH/64, CC/64, 1), cb>>>(wk, wqkvt + (size_t)CC*CC,     CC, KVH*DH, 0, 0);
    wconv2<<<dim3(KVH*DH/64, CC/64, 1), cb>>>(wv, wqkvt + (size_t)(CC+KVH*DH)*CC, CC, KVH*DH, 0, 0);
    wconv2<<<dim3(CC/64,  CC/64, 1), cb>>>(wo,  wot,  CC, CC, 0, 0);
    wconv2<<<dim3(FF/64,  CC/64, 1), cb>>>(sw1, sw12t,                 CC, FF, 0, 0);
    wconv2<<<dim3(FF/64,  CC/64, 1), cb>>>(sw2, sw12t + (size_t)FF*CC, CC, FF, 0, 0);
    wconv2<<<dim3(CC/64,  FF/64, 1), cb>>>(sw3, sw3t, FF, CC, 0, 0);
    wconv2<<<dim3(FF/64,  CC/64, EE), cb>>>(ew1, ew12t,                 CC, FF, (long)CC*FF, (long)2*FF*CC);
    wconv2<<<dim3(FF/64,  CC/64, EE), cb>>>(ew2, ew12t + (size_t)FF*CC, CC, FF, (long)CC*FF, (long)2*FF*CC);
    wconv2<<<dim3(CC/64,  FF/64, EE), cb>>>(ew3, ew3t, FF, CC, (long)FF*CC, (long)CC*FF);

    // 1) pre-attn norm
    rmsnorm_kernel<<<NTOK, 256>>>(x, ln1, nullptr, xnb);
    // 2) fused QKV projection
    gemm_mma<<<dim3(QKVN/128, NTOK/128), 256>>>(xnb, wqkvt, qkv, NTOK, QKVN, CC);
    // 3) RoPE (q then k, inside fused buffer)
    rope_kernel<<<(NTOK * HH * 32 + 255) / 256, 256>>>(qkv, HH, 0);
    rope_kernel<<<(NTOK * KVH * 32 + 255) / 256, 256>>>(qkv, KVH, CC);
    // 4) attention
    attn_kernel<<<dim3(TT/64, HH, BB), 64>>>(qkv, aob);
    // 5) output projection + ReZero residual
    gemm_mma<<<dim3(CC/128, NTOK/128), 256>>>(aob, wot, proj, NTOK, CC, CC);
    resadd_kernel<<<(OUT_MAIN + 255) / 256, 256>>>(x, proj, a_attn, h);
    // 6) post-attn norm
    rmsnorm_kernel<<<NTOK, 256>>>(h, ln2, xf, xfb);
    // 7) routing + aux + compaction
    route_kernel<<<NTOK / 4, 128>>>(xf, gatew);
    aux_kernel<<<1, 256>>>();
    zero_cnt_kernel<<<1, 32>>>();
    count_kernel<<<(NTOK + 255) / 256, 256>>>();
    offsets_kernel<<<1, 32>>>();
    assign_kernel<<<(NTOK + 255) / 256, 256>>>();
    // 8) shared expert SwiGLU (fused w1|w2)
    gemm_mma<<<dim3(2*FF/128, NTOK/128), 256>>>(xfb, sw12t, g12, NTOK, 2*FF, CC);
    silu_mul_kernel<<<(int)(((long)NTOK * FF + 255) / 256), 256>>>(g12, g1b, NTOK, nullptr);
    gemm_mma<<<dim3(CC/128, NTOK/128), 256>>>(g1b, sw3t, moe, NTOK, CC, FF);
    // 9) routed experts, batched across all experts
    gather_all_kernel<<<ECAP, 128>>>(xgb, xfb);
    gemm_moe<<<dim3(2*FF/128, ECAP/128), 256>>>(xgb, ew12t, g12, 2*FF, CC, (long)2*FF*CC);
    {
        void* op; cudaGetSymbolAddress(&op, g_off);
        const int* totalPtr = ((const int*)op) + EE;
        silu_mul_kernel<<<(int)(((long)ECAP * FF + 255) / 256), 256>>>(g12, g1b, 0, totalPtr);
    }
    gemm_moe<<<dim3(CC/128, ECAP/128), 256>>>(g1b, ew3t, eo, CC, FF, (long)CC*FF);
    // 10) final combine (deterministic, no atomics) + aux scalar
    final_kernel<<<NTOK, 256>>>(h, moe, eo, a_moe, out);
    if (out_size > OUT_MAIN) auxwrite_kernel<<<1, 1>>>(out);
}

// round 6
// speedup vs baseline: 2.0502x; 1.6272x over previous
#include <cuda_runtime.h>
#include <cuda_bf16.h>
#include <math.h>
#include <stdint.h>

// Problem constants
#define BB   2
#define TT   2048
#define CC   1024
#define HH   16
#define KVH  4
#define DH   64
#define NREP 4
#define FF   4096
#define EE   8
#define TOPK 2
#define WIN  1024
#define NTOK (BB*TT)            // 4096
#define OUT_MAIN (NTOK*CC)      // 4194304
#define QKVN (CC + 2*KVH*DH)    // 1536
#define ECAP 9216               // 8192 real rows + padding, 128-aligned

// ---------------- scratch (device globals; no allocation) ----------------
__device__ float g_qkv [NTOK*QKVN];
__device__ float g_proj[NTOK*CC];
__device__ float g_h   [NTOK*CC];
__device__ float g_xf  [NTOK*CC];
__device__ float g_moe [NTOK*CC];
__device__ float g_eo  [(size_t)ECAP*CC];
__device__ float g_probs[NTOK*EE];
__device__ float g_lse2[NTOK];
__device__ int   g_sel [NTOK*2];
__device__ float g_selw[NTOK*2];
__device__ int   g_cnt [EE];
__device__ int   g_cnt2[EE];
__device__ int   g_off [EE+1];
__device__ int   g_idx [ECAP];
__device__ int   g_tokrow[NTOK*2];
__device__ float g_aux;

// bf16 activations
__device__ __nv_bfloat16 g_xnb [NTOK*CC];
__device__ __nv_bfloat16 g_aob [NTOK*CC];
__device__ __nv_bfloat16 g_xfb [NTOK*CC];
__device__ __nv_bfloat16 g_xgb [(size_t)ECAP*CC];
__device__ __nv_bfloat16 g_g1b [(size_t)ECAP*FF];

// bf16 transposed weights [N,K] (w12 interleaved: w1->2f, w2->2f+1)
__device__ __nv_bfloat16 g_wqkvt[QKVN*CC];
__device__ __nv_bfloat16 g_wot  [CC*CC];
__device__ __nv_bfloat16 g_sw12t[2*FF*CC];
__device__ __nv_bfloat16 g_sw3t [CC*FF];
__device__ __nv_bfloat16 g_ew12t[(size_t)EE*2*FF*CC];
__device__ __nv_bfloat16 g_ew3t [(size_t)EE*CC*FF];

__device__ __forceinline__ uint32_t su32(const void* p) {
    uint32_t a;
    asm("{ .reg .u64 t; cvta.to.shared.u64 t, %1; cvt.u32.u64 %0, t; }" : "=r"(a) : "l"(p));
    return a;
}
__device__ __forceinline__ uint32_t packbf(float a, float b) {
    __nv_bfloat162 t = __floats2bfloat162_rn(a, b);
    return *(uint32_t*)&t;
}

#define CP_ASYNC16(d, s) asm volatile("cp.async.cg.shared.global [%0], [%1], 16;" :: "r"(d), "l"(s))
#define CP_COMMIT()      asm volatile("cp.async.commit_group;" ::: "memory")
#define CP_WAIT(n)       asm volatile("cp.async.wait_group %0;" :: "n"(n) : "memory")

#define BM 128
#define BN 128
#define BK 32
#define ASTR 40   // padded row stride in bf16 elems

// ================= GEMM mainloop (no epilogue) ===========================
#define GEMM_MAIN(A_, Bt_, K_)                                                 \
    __shared__ __align__(16) __nv_bfloat16 sA[2][BM * ASTR];                   \
    __shared__ __align__(16) __nv_bfloat16 sB[2][BM * ASTR];                   \
    int tid = threadIdx.x;                                                     \
    int wid = tid >> 5, lane = tid & 31;                                       \
    int wm = wid >> 2, wn = wid & 3;                                           \
    float cr[4][4][4];                                                         \
    _Pragma("unroll") for (int i = 0; i < 4; i++)                              \
    _Pragma("unroll") for (int j = 0; j < 4; j++)                              \
    _Pragma("unroll") for (int r = 0; r < 4; r++) cr[i][j][r] = 0.f;           \
    int lrow = tid >> 1;                                                       \
    int lc16 = (tid & 1) * 16;                                                 \
    int nCh = (K_) / BK;                                                       \
    {                                                                          \
        const __nv_bfloat16* srcA0 = (A_) + (size_t)(rowBase + lrow) * (K_) + lc16; \
        const __nv_bfloat16* srcB0 = (Bt_) + (size_t)(colBase + lrow) * (K_) + lc16; \
        uint32_t dA0 = su32(&sA[0][lrow * ASTR + lc16]);                       \
        uint32_t dB0 = su32(&sB[0][lrow * ASTR + lc16]);                       \
        CP_ASYNC16(dA0, srcA0); CP_ASYNC16(dA0 + 16, srcA0 + 8);               \
        CP_ASYNC16(dB0, srcB0); CP_ASYNC16(dB0 + 16, srcB0 + 8);               \
        CP_COMMIT();                                                           \
    }                                                                          \
    for (int ch = 0; ch < nCh; ch++) {                                         \
        int st = ch & 1;                                                       \
        if (ch + 1 < nCh) {                                                    \
            int k0 = (ch + 1) * BK;                                            \
            const __nv_bfloat16* srcA = (A_) + (size_t)(rowBase + lrow) * (K_) + k0 + lc16; \
            const __nv_bfloat16* srcB = (Bt_) + (size_t)(colBase + lrow) * (K_) + k0 + lc16; \
            uint32_t dA = su32(&sA[st ^ 1][lrow * ASTR + lc16]);               \
            uint32_t dB = su32(&sB[st ^ 1][lrow * ASTR + lc16]);               \
            CP_ASYNC16(dA, srcA); CP_ASYNC16(dA + 16, srcA + 8);               \
            CP_ASYNC16(dB, srcB); CP_ASYNC16(dB + 16, srcB + 8);               \
            CP_COMMIT(); CP_WAIT(1);                                           \
        } else { CP_WAIT(0); }                                                 \
        __syncthreads();                                                       \
        int r16 = lane & 15, kh = lane >> 4;                                   \
        int rn = lane & 7, knh = (lane >> 3) & 1;                              \
        _Pragma("unroll") for (int kk = 0; kk < 2; kk++) {                     \
            uint32_t af[4][4];                                                 \
            _Pragma("unroll") for (int mf = 0; mf < 4; mf++) {                 \
                uint32_t ad = su32(&sA[st][(wm * 64 + mf * 16 + r16) * ASTR + kk * 16 + kh * 8]); \
                asm volatile("ldmatrix.sync.aligned.m8n8.x4.shared.b16 {%0,%1,%2,%3}, [%4];" \
                    : "=r"(af[mf][0]), "=r"(af[mf][1]), "=r"(af[mf][2]), "=r"(af[mf][3]) : "r"(ad)); \
            }                                                                  \
            uint32_t bfr[4][2];                                                \
            _Pragma("unroll") for (int nf = 0; nf < 4; nf++) {                 \
                uint32_t bd = su32(&sB[st][(wn * 32 + nf * 8 + rn) * ASTR + kk * 16 + knh * 8]); \
                asm volatile("ldmatrix.sync.aligned.m8n8.x2.shared.b16 {%0,%1}, [%2];" \
                    : "=r"(bfr[nf][0]), "=r"(bfr[nf][1]) : "r"(bd));           \
            }                                                                  \
            _Pragma("unroll") for (int mf = 0; mf < 4; mf++)                   \
            _Pragma("unroll") for (int nf = 0; nf < 4; nf++) {                 \
                asm volatile(                                                  \
                    "mma.sync.aligned.m16n8k16.row.col.f32.bf16.bf16.f32 "     \
                    "{%0,%1,%2,%3}, {%4,%5,%6,%7}, {%8,%9}, {%0,%1,%2,%3};"    \
                    : "+f"(cr[mf][nf][0]), "+f"(cr[mf][nf][1]),                \
                      "+f"(cr[mf][nf][2]), "+f"(cr[mf][nf][3])                 \
                    : "r"(af[mf][0]), "r"(af[mf][1]), "r"(af[mf][2]), "r"(af[mf][3]), \
                      "r"(bfr[nf][0]), "r"(bfr[nf][1]));                       \
            }                                                                  \
        }                                                                      \
        __syncthreads();                                                       \
    }                                                                          \
    int rr = lane >> 2, cq = (lane & 3) * 2;

// ================= dense GEMM, fp32 out =================
__global__ __launch_bounds__(256) void gemm_mma(
    const __nv_bfloat16* __restrict__ A, const __nv_bfloat16* __restrict__ Bt,
    float* __restrict__ C, int N, int K)
{
    int rowBase = blockIdx.y * BM, colBase = blockIdx.x * BN;
    GEMM_MAIN(A, Bt, K)
#pragma unroll
    for (int mf = 0; mf < 4; mf++)
#pragma unroll
        for (int nf = 0; nf < 4; nf++) {
            int row0 = rowBase + wm * 64 + mf * 16 + rr;
            int col = colBase + wn * 32 + nf * 8 + cq;
            *(float2*)&C[(size_t)row0 * N + col] = make_float2(cr[mf][nf][0], cr[mf][nf][1]);
            *(float2*)&C[(size_t)(row0 + 8) * N + col] = make_float2(cr[mf][nf][2], cr[mf][nf][3]);
        }
}

// ================= dense GEMM, fused SwiGLU bf16 out (interleaved w12) ===
__global__ __launch_bounds__(256) void gemm_swiglu(
    const __nv_bfloat16* __restrict__ A, const __nv_bfloat16* __restrict__ Bt,
    __nv_bfloat16* __restrict__ Obf, int N2, int K)
{
    int rowBase = blockIdx.y * BM, colBase = blockIdx.x * BN;
    GEMM_MAIN(A, Bt, K)
    int FFo = N2 >> 1;
#pragma unroll
    for (int mf = 0; mf < 4; mf++)
#pragma unroll
        for (int nf = 0; nf < 4; nf++) {
            int row0 = rowBase + wm * 64 + mf * 16 + rr;
            int f = (colBase + wn * 32 + nf * 8 + cq) >> 1;
            float a0 = cr[mf][nf][0], b0 = cr[mf][nf][1];
            Obf[(size_t)row0 * FFo + f] = __float2bfloat16(a0 / (1.f + __expf(-a0)) * b0);
            float a1 = cr[mf][nf][2], b1 = cr[mf][nf][3];
            Obf[(size_t)(row0 + 8) * FFo + f] = __float2bfloat16(a1 / (1.f + __expf(-a1)) * b1);
        }
}

// ================= MoE GEMM, fp32 out =================
__global__ __launch_bounds__(256) void gemm_moe(
    const __nv_bfloat16* __restrict__ A, const __nv_bfloat16* __restrict__ Wb,
    float* __restrict__ C, int N, int K, long wstride)
{
    int rowBase = blockIdx.y * BM;
    if (rowBase >= g_off[EE]) return;
    int colBase = blockIdx.x * BN;
    int e = 0;
    while (g_off[e + 1] <= rowBase) e++;
    const __nv_bfloat16* Bt = Wb + (size_t)e * wstride;
    GEMM_MAIN(A, Bt, K)
#pragma unroll
    for (int mf = 0; mf < 4; mf++)
#pragma unroll
        for (int nf = 0; nf < 4; nf++) {
            int row0 = rowBase + wm * 64 + mf * 16 + rr;
            int col = colBase + wn * 32 + nf * 8 + cq;
            *(float2*)&C[(size_t)row0 * N + col] = make_float2(cr[mf][nf][0], cr[mf][nf][1]);
            *(float2*)&C[(size_t)(row0 + 8) * N + col] = make_float2(cr[mf][nf][2], cr[mf][nf][3]);
        }
}

// ================= MoE GEMM, fused SwiGLU bf16 out =================
__global__ __launch_bounds__(256) void gemm_moe_swiglu(
    const __nv_bfloat16* __restrict__ A, const __nv_bfloat16* __restrict__ Wb,
    __nv_bfloat16* __restrict__ Obf, int N2, int K, long wstride)
{
    int rowBase = blockIdx.y * BM;
    if (rowBase >= g_off[EE]) return;
    int colBase = blockIdx.x * BN;
    int e = 0;
    while (g_off[e + 1] <= rowBase) e++;
    const __nv_bfloat16* Bt = Wb + (size_t)e * wstride;
    GEMM_MAIN(A, Bt, K)
    int FFo = N2 >> 1;
#pragma unroll
    for (int mf = 0; mf < 4; mf++)
#pragma unroll
        for (int nf = 0; nf < 4; nf++) {
            int row0 = rowBase + wm * 64 + mf * 16 + rr;
            int f = (colBase + wn * 32 + nf * 8 + cq) >> 1;
            float a0 = cr[mf][nf][0], b0 = cr[mf][nf][1];
            Obf[(size_t)row0 * FFo + f] = __float2bfloat16(a0 / (1.f + __expf(-a0)) * b0);
            float a1 = cr[mf][nf][2], b1 = cr[mf][nf][3];
            Obf[(size_t)(row0 + 8) * FFo + f] = __float2bfloat16(a1 / (1.f + __expf(-a1)) * b1);
        }
}

// ---------------- weight transpose+convert with row interleave ----------
// W[K,N] f32 -> Wt[n*rs+ro, K] bf16
__global__ void wconv2(const float* __restrict__ W, __nv_bfloat16* __restrict__ Wt,
                       int K, int N, long sstride, long dstride, int rs, int ro) {
    __shared__ float t[64][65];
    const float* Wz = W + (size_t)blockIdx.z * sstride;
    __nv_bfloat16* Wtz = Wt + (size_t)blockIdx.z * dstride;
    int n0 = blockIdx.x * 64, k0 = blockIdx.y * 64;
    int tid = threadIdx.x;
    int rrw = tid >> 4;
    int c4 = (tid & 15) * 4;
#pragma unroll
    for (int r = 0; r < 64; r += 16) {
        float4 v = *(const float4*)&Wz[(size_t)(k0 + r + rrw) * N + n0 + c4];
        t[r + rrw][c4 + 0] = v.x; t[r + rrw][c4 + 1] = v.y;
        t[r + rrw][c4 + 2] = v.z; t[r + rrw][c4 + 3] = v.w;
    }
    __syncthreads();
    int nl = tid >> 3;
    int c8 = (tid & 7) * 8;
#pragma unroll
    for (int r = 0; r < 64; r += 32) {
        int n = nl + r;
        __nv_bfloat16 o[8];
#pragma unroll
        for (int j = 0; j < 8; j++) o[j] = __float2bfloat16(t[c8 + j][n]);
        *(uint4*)&Wtz[((size_t)(n0 + n) * rs + ro) * K + k0 + c8] = *(uint4*)o;
    }
}

// ---------------- RMSNorm (dual output) ----------------
__global__ void rmsnorm_kernel(const float* __restrict__ x,
                               const float* __restrict__ w,
                               float* __restrict__ of,
                               __nv_bfloat16* __restrict__ ob) {
    int row = blockIdx.x;
    int tid = threadIdx.x;
    const float* xr = x + (size_t)row * CC;
    float s = 0.f;
    for (int i = tid; i < CC; i += 256) { float v = xr[i]; s += v * v; }
    __shared__ float red[256];
    red[tid] = s; __syncthreads();
    for (int o2 = 128; o2 > 0; o2 >>= 1) {
        if (tid < o2) red[tid] += red[tid + o2];
        __syncthreads();
    }
    float scale = rsqrtf(red[0] / (float)CC + 1e-6f);
    for (int i = tid; i < CC; i += 256) {
        float v = xr[i] * scale * w[i];
        if (of) of[(size_t)row * CC + i] = v;
        ob[(size_t)row * CC + i] = __float2bfloat16(v);
    }
}

// ---------------- RoPE (in place in qkv buffer) --------------------------
__global__ void rope_kernel(float* __restrict__ X, int nheads, int hoff) {
    int i = blockIdx.x * blockDim.x + threadIdx.x;
    int total = NTOK * nheads * 32;
    if (i >= total) return;
    int p = i & 31;
    int tmp = i >> 5;
    int hh = tmp % nheads;
    int row = tmp / nheads;
    int t = row % TT;
    float invf = expf(-(float)p * (logf(10000.f) / 32.f));
    float ang = (float)t * invf;
    float cs = cosf(ang), sn = sinf(ang);
    size_t base = (size_t)row * QKVN + hoff + hh * 64;
    float a = X[base + p];
    float b = X[base + p + 32];
    X[base + p]      = a * cs - b * sn;
    X[base + p + 32] = b * cs + a * sn;
}

// ---------------- flash attention: mma.sync bf16, online softmax ---------
// grid (TT/64, HH, BB), 128 threads (4 warps, 16 q rows each)
__global__ __launch_bounds__(128) void attn_mma(const float* __restrict__ QKV,
                                                __nv_bfloat16* __restrict__ O) {
    int qb = blockIdx.x, h = blockIdx.y, b = blockIdx.z;
    int tid = threadIdx.x;
    int wid = tid >> 5, lane = tid & 31;
    int kvh = h / NREP;

    __shared__ __align__(16) __nv_bfloat16 Qs[64 * 72];
    __shared__ __align__(16) __nv_bfloat16 Ks[64 * 72];
    __shared__ __align__(16) __nv_bfloat16 Vt[64 * 72];

    // load Q tile (scaled by 1/8)
    for (int i = tid; i < 64 * 32; i += 128) {
        int row = i >> 5, p2 = i & 31;
        const float* src = QKV + ((size_t)(b * TT + qb * 64 + row)) * QKVN + h * DH + p2 * 2;
        *(__nv_bfloat162*)&Qs[row * 72 + p2 * 2] =
            __floats2bfloat162_rn(src[0] * 0.125f, src[1] * 0.125f);
    }
    __syncthreads();

    int r16 = lane & 15, kh = lane >> 4;
    int rn = lane & 7, knh = (lane >> 3) & 1;
    uint32_t qf[4][4];
#pragma unroll
    for (int kk = 0; kk < 4; kk++) {
        uint32_t ad = su32(&Qs[(wid * 16 + r16) * 72 + kk * 16 + kh * 8]);
        asm volatile("ldmatrix.sync.aligned.m8n8.x4.shared.b16 {%0,%1,%2,%3}, [%4];"
            : "=r"(qf[kk][0]), "=r"(qf[kk][1]), "=r"(qf[kk][2]), "=r"(qf[kk][3]) : "r"(ad));
    }

    int rr = lane >> 2, cq = (lane & 3) * 2;
    int t0 = qb * 64 + wid * 16 + rr;   // second row = t0+8
    float m0 = -1e30f, m1 = -1e30f, l0 = 0.f, l1 = 0.f;
    float acc[8][4];
#pragma unroll
    for (int dn = 0; dn < 8; dn++)
#pragma unroll
        for (int r = 0; r < 4; r++) acc[dn][r] = 0.f;

    int kstart = qb * 64 - WIN; if (kstart < 0) kstart = 0;
    for (int k0 = kstart; k0 <= qb * 64; k0 += 64) {
        __syncthreads();
        for (int i = tid; i < 64 * 32; i += 128) {
            int row = i >> 5, p2 = i & 31;
            const float* kv = QKV + ((size_t)(b * TT + k0 + row)) * QKVN + CC + kvh * DH;
            *(__nv_bfloat162*)&Ks[row * 72 + p2 * 2] =
                __floats2bfloat162_rn(kv[p2 * 2], kv[p2 * 2 + 1]);
            const float* vv = kv + KVH * DH;
            Vt[(p2 * 2) * 72 + row]     = __float2bfloat16(vv[p2 * 2]);
            Vt[(p2 * 2 + 1) * 72 + row] = __float2bfloat16(vv[p2 * 2 + 1]);
        }
        __syncthreads();

        float s[8][4];
#pragma unroll
        for (int j = 0; j < 8; j++) {
            s[j][0] = s[j][1] = s[j][2] = s[j][3] = 0.f;
#pragma unroll
            for (int kk = 0; kk < 4; kk++) {
                uint32_t bfr[2];
                uint32_t bd = su32(&Ks[(j * 8 + rn) * 72 + kk * 16 + knh * 8]);
                asm volatile("ldmatrix.sync.aligned.m8n8.x2.shared.b16 {%0,%1}, [%2];"
                    : "=r"(bfr[0]), "=r"(bfr[1]) : "r"(bd));
                asm volatile(
                    "mma.sync.aligned.m16n8k16.row.col.f32.bf16.bf16.f32 "
                    "{%0,%1,%2,%3}, {%4,%5,%6,%7}, {%8,%9}, {%0,%1,%2,%3};"
                    : "+f"(s[j][0]), "+f"(s[j][1]), "+f"(s[j][2]), "+f"(s[j][3])
                    : "r"(qf[kk][0]), "r"(qf[kk][1]), "r"(qf[kk][2]), "r"(qf[kk][3]),
                      "r"(bfr[0]), "r"(bfr[1]));
            }
        }
        // mask (causal + window)
#pragma unroll
        for (int j = 0; j < 8; j++) {
            int kg = k0 + j * 8 + cq;
            if (kg > t0 || kg < t0 - WIN) s[j][0] = -1e30f;
            if (kg + 1 > t0 || kg + 1 < t0 - WIN) s[j][1] = -1e30f;
            if (kg > t0 + 8 || kg < t0 + 8 - WIN) s[j][2] = -1e30f;
            if (kg + 1 > t0 + 8 || kg + 1 < t0 + 8 - WIN) s[j][3] = -1e30f;
        }
        // row max across fragment + quad lanes
        float mx0 = -1e30f, mx1 = -1e30f;
#pragma unroll
        for (int j = 0; j < 8; j++) {
            mx0 = fmaxf(mx0, fmaxf(s[j][0], s[j][1]));
            mx1 = fmaxf(mx1, fmaxf(s[j][2], s[j][3]));
        }
        mx0 = fmaxf(mx0, __shfl_xor_sync(0xffffffffu, mx0, 1));
        mx0 = fmaxf(mx0, __shfl_xor_sync(0xffffffffu, mx0, 2));
        mx1 = fmaxf(mx1, __shfl_xor_sync(0xffffffffu, mx1, 1));
        mx1 = fmaxf(mx1, __shfl_xor_sync(0xffffffffu, mx1, 2));
        float mn0 = fmaxf(m0, mx0), mn1 = fmaxf(m1, mx1);
        float c0 = __expf(m0 - mn0), c1 = __expf(m1 - mn1);
        m0 = mn0; m1 = mn1;
        l0 *= c0; l1 *= c1;
#pragma unroll
        for (int dn = 0; dn < 8; dn++) {
            acc[dn][0] *= c0; acc[dn][1] *= c0;
            acc[dn][2] *= c1; acc[dn][3] *= c1;
        }
#pragma unroll
        for (int j = 0; j < 8; j++) {
            s[j][0] = __expf(s[j][0] - m0); s[j][1] = __expf(s[j][1] - m0);
            s[j][2] = __expf(s[j][2] - m1); s[j][3] = __expf(s[j][3] - m1);
            l0 += s[j][0] + s[j][1];
            l1 += s[j][2] + s[j][3];
        }
        uint32_t pa[4][4];
#pragma unroll
        for (int kk = 0; kk < 4; kk++) {
            int j0 = kk * 2, j1 = kk * 2 + 1;
            pa[kk][0] = packbf(s[j0][0], s[j0][1]);
            pa[kk][1] = packbf(s[j0][2], s[j0][3]);
            pa[kk][2] = packbf(s[j1][0], s[j1][1]);
            pa[kk][3] = packbf(s[j1][2], s[j1][3]);
        }
#pragma unroll
        for (int dn = 0; dn < 8; dn++)
#pragma unroll
            for (int kk = 0; kk < 4; kk++) {
                uint32_t bfr[2];
                uint32_t bd = su32(&Vt[(dn * 8 + rn) * 72 + kk * 16 + knh * 8]);
                asm volatile("ldmatrix.sync.aligned.m8n8.x2.shared.b16 {%0,%1}, [%2];"
                    : "=r"(bfr[0]), "=r"(bfr[1]) : "r"(bd));
                asm volatile(
                    "mma.sync.aligned.m16n8k16.row.col.f32.bf16.bf16.f32 "
                    "{%0,%1,%2,%3}, {%4,%5,%6,%7}, {%8,%9}, {%0,%1,%2,%3};"
                    : "+f"(acc[dn][0]), "+f"(acc[dn][1]), "+f"(acc[dn][2]), "+f"(acc[dn][3])
                    : "r"(pa[kk][0]), "r"(pa[kk][1]), "r"(pa[kk][2]), "r"(pa[kk][3]),
                      "r"(bfr[0]), "r"(bfr[1]));
            }
    }
    l0 += __shfl_xor_sync(0xffffffffu, l0, 1);
    l0 += __shfl_xor_sync(0xffffffffu, l0, 2);
    l1 += __shfl_xor_sync(0xffffffffu, l1, 1);
    l1 += __shfl_xor_sync(0xffffffffu, l1, 2);
    float i0 = 1.f / l0, i1 = 1.f / l1;
    __nv_bfloat16* o0 = O + ((size_t)(b * TT + t0)) * CC + h * DH;
    __nv_bfloat16* o1 = o0 + (size_t)8 * CC;
#pragma unroll
    for (int dn = 0; dn < 8; dn++) {
        *(__nv_bfloat162*)&o0[dn * 8 + cq] =
            __floats2bfloat162_rn(acc[dn][0] * i0, acc[dn][1] * i0);
        *(__nv_bfloat162*)&o1[dn * 8 + cq] =
            __floats2bfloat162_rn(acc[dn][2] * i1, acc[dn][3] * i1);
    }
}

// ---------------- residual add ----------------
__global__ void resadd_kernel(const float* __restrict__ x,
                              const float* __restrict__ y,
                              const float* __restrict__ alpha,
                              float* __restrict__ o) {
    int i = blockIdx.x * blockDim.x + threadIdx.x;
    if (i >= OUT_MAIN) return;
    o[i] = x[i] + (*alpha) * y[i];
}

// ---------------- router ----------------
__global__ void route_kernel(const float* __restrict__ xf,
                             const float* __restrict__ gw) {
    int warp = threadIdx.x >> 5, lane = threadIdx.x & 31;
    int tok = blockIdx.x * 4 + warp;
    if (tok >= NTOK) return;
    const float* xr = xf + (size_t)tok * CC;
    float part[EE];
#pragma unroll
    for (int e = 0; e < EE; e++) part[e] = 0.f;
    for (int d = lane; d < CC; d += 32) {
        float xv = xr[d];
#pragma unroll
        for (int e = 0; e < EE; e++) part[e] += xv * gw[d * EE + e];
    }
#pragma unroll
    for (int e = 0; e < EE; e++)
#pragma unroll
        for (int o = 16; o > 0; o >>= 1)
            part[e] += __shfl_xor_sync(0xffffffffu, part[e], o);
    if (lane == 0) {
        float v0 = -1e30f; int i0 = 0;
#pragma unroll
        for (int e = 0; e < EE; e++) if (part[e] > v0) { v0 = part[e]; i0 = e; }
        float v1 = -1e30f; int i1 = 0;
#pragma unroll
        for (int e = 0; e < EE; e++)
            if (e != i0 && part[e] > v1) { v1 = part[e]; i1 = e; }
        float ex = expf(v1 - v0);
        float w0 = 1.f / (1.f + ex);
        float w1 = ex / (1.f + ex);
        g_sel[tok * 2] = i0; g_sel[tok * 2 + 1] = i1;
        g_selw[tok * 2] = w0; g_selw[tok * 2 + 1] = w1;
        float mx = v0, sum = 0.f, pe[EE];
#pragma unroll
        for (int e = 0; e < EE; e++) { pe[e] = expf(part[e] - mx); sum += pe[e]; }
#pragma unroll
        for (int e = 0; e < EE; e++) g_probs[tok * EE + e] = pe[e] / sum;
        float lse = mx + logf(sum);
        g_lse2[tok] = lse * lse;
    }
}

// ---------------- aux loss ----------------
__global__ void aux_kernel() {
    __shared__ float red[256];
    int tid = threadIdx.x;
    float loadv[EE];
#pragma unroll
    for (int e = 0; e < EE; e++) loadv[e] = 0.f;
    for (int n = tid; n < NTOK; n += 256) {
#pragma unroll
        for (int e = 0; e < EE; e++) loadv[e] += g_probs[n * EE + e];
    }
    float loads[EE];
    for (int e = 0; e < EE; e++) {
        red[tid] = loadv[e]; __syncthreads();
        for (int o = 128; o > 0; o >>= 1) {
            if (tid < o) red[tid] += red[tid + o];
            __syncthreads();
        }
        loads[e] = red[0]; __syncthreads();
    }
    float zp = 0.f;
    for (int n = tid; n < NTOK; n += 256) zp += g_lse2[n];
    red[tid] = zp; __syncthreads();
    for (int o = 128; o > 0; o >>= 1) {
        if (tid < o) red[tid] += red[tid + o];
        __syncthreads();
    }
    if (tid == 0) {
        float tot = 0.f;
        for (int e = 0; e < EE; e++) tot += loads[e];
        float lb = 0.f;
        for (int e = 0; e < EE; e++) { float f = loads[e] / tot; lb += f * f; }
        lb *= (float)EE;
        float z = red[0] / (float)NTOK;
        g_aux = 0.01f * lb + 0.001f * z;
    }
}

__global__ void zero_cnt_kernel() { if (threadIdx.x < EE) g_cnt[threadIdx.x] = 0; }

__global__ void count_kernel() {
    int i = blockIdx.x * blockDim.x + threadIdx.x;
    if (i >= NTOK) return;
#pragma unroll
    for (int kk = 0; kk < TOPK; kk++)
        atomicAdd(&g_cnt[g_sel[i * 2 + kk]], 1);
}

__global__ void offsets_kernel() {
    if (threadIdx.x == 0) {
        int acc = 0;
        for (int e = 0; e < EE; e++) {
            g_off[e] = acc;
            acc += (g_cnt[e] + BM - 1) & ~(BM - 1);
            g_cnt2[e] = 0;
        }
        g_off[EE] = acc;
    }
}

__global__ void assign_kernel() {
    int i = blockIdx.x * blockDim.x + threadIdx.x;
    if (i >= NTOK) return;
#pragma unroll
    for (int kk = 0; kk < TOPK; kk++) {
        int e = g_sel[i * 2 + kk];
        int pos = atomicAdd(&g_cnt2[e], 1);
        int row = g_off[e] + pos;
        g_idx[row] = i;
        g_tokrow[i * 2 + kk] = row;
    }
}

__global__ void gather_all_kernel(__nv_bfloat16* __restrict__ dst,
                                  const __nv_bfloat16* __restrict__ src) {
    int b = blockIdx.x;
    if (b >= g_off[EE]) return;
    int e = 0;
    while (g_off[e + 1] <= b) e++;
    if (b - g_off[e] >= g_cnt[e]) return;
    int t = g_idx[b];
    uint4* d4 = (uint4*)(dst + (size_t)b * CC);
    const uint4* s4 = (const uint4*)(src + (size_t)t * CC);
    int i = threadIdx.x;
    if (i < CC * 2 / 16) d4[i] = s4[i];
}

// final: out = h + a_moe * (shared + w0*eo[r0] + w1*eo[r1])
__global__ void final_kernel(const float* __restrict__ h, const float* __restrict__ moe,
                             const float* __restrict__ eo,
                             const float* __restrict__ alpha, float* __restrict__ out) {
    int t = blockIdx.x;
    float w0 = g_selw[t * 2], w1 = g_selw[t * 2 + 1];
    int r0 = g_tokrow[t * 2], r1 = g_tokrow[t * 2 + 1];
    float a = *alpha;
    const float* hr = h + (size_t)t * CC;
    const float* mr = moe + (size_t)t * CC;
    const float* e0 = eo + (size_t)r0 * CC;
    const float* e1 = eo + (size_t)r1 * CC;
    float* orow = out + (size_t)t * CC;
    for (int i = threadIdx.x; i < CC; i += blockDim.x)
        orow[i] = hr[i] + a * (mr[i] + w0 * e0[i] + w1 * e1[i]);
}

__global__ void auxwrite_kernel(float* __restrict__ out) { out[OUT_MAIN] = g_aux; }

// ---------------- launch ----------------
extern "C" void kernel_launch(void* const* d_in, const int* in_sizes, int n_in,
                              void* d_out, int out_size) {
    const float* x      = (const float*)d_in[0];
    const float* ln1    = (const float*)d_in[1];
    const float* ln2    = (const float*)d_in[2];
    const float* wq     = (const float*)d_in[3];
    const float* wk     = (const float*)d_in[4];
    const float* wv     = (const float*)d_in[5];
    const float* wo     = (const float*)d_in[6];
    const float* sw1    = (const float*)d_in[7];
    const float* sw2    = (const float*)d_in[8];
    const float* sw3    = (const float*)d_in[9];
    const float* ew1    = (const float*)d_in[10];
    const float* ew2    = (const float*)d_in[11];
    const float* ew3    = (const float*)d_in[12];
    const float* gatew  = (const float*)d_in[13];
    const float* a_attn = (const float*)d_in[14];
    const float* a_moe  = (const float*)d_in[15];
    float* out = (float*)d_out;

    void* p;
    float *qkv, *proj, *h, *xf, *moe, *eo;
    __nv_bfloat16 *xnb, *aob, *xfb, *xgb, *g1b;
    __nv_bfloat16 *wqkvt, *wot, *sw12t, *sw3t, *ew12t, *ew3t;
    cudaGetSymbolAddress(&p, g_qkv);  qkv  = (float*)p;
    cudaGetSymbolAddress(&p, g_proj); proj = (float*)p;
    cudaGetSymbolAddress(&p, g_h);    h    = (float*)p;
    cudaGetSymbolAddress(&p, g_xf);   xf   = (float*)p;
    cudaGetSymbolAddress(&p, g_moe);  moe  = (float*)p;
    cudaGetSymbolAddress(&p, g_eo);   eo   = (float*)p;
    cudaGetSymbolAddress(&p, g_xnb);  xnb  = (__nv_bfloat16*)p;
    cudaGetSymbolAddress(&p, g_aob);  aob  = (__nv_bfloat16*)p;
    cudaGetSymbolAddress(&p, g_xfb);  xfb  = (__nv_bfloat16*)p;
    cudaGetSymbolAddress(&p, g_xgb);  xgb  = (__nv_bfloat16*)p;
    cudaGetSymbolAddress(&p, g_g1b);  g1b  = (__nv_bfloat16*)p;
    cudaGetSymbolAddress(&p, g_wqkvt); wqkvt = (__nv_bfloat16*)p;
    cudaGetSymbolAddress(&p, g_wot);   wot   = (__nv_bfloat16*)p;
    cudaGetSymbolAddress(&p, g_sw12t); sw12t = (__nv_bfloat16*)p;
    cudaGetSymbolAddress(&p, g_sw3t);  sw3t  = (__nv_bfloat16*)p;
    cudaGetSymbolAddress(&p, g_ew12t); ew12t = (__nv_bfloat16*)p;
    cudaGetSymbolAddress(&p, g_ew3t);  ew3t  = (__nv_bfloat16*)p;

    dim3 cb(256);
    // weight conversion; w12 column-interleaved (w1->2f, w2->2f+1)
    wconv2<<<dim3(CC/64,  CC/64, 1), cb>>>(wq,  wqkvt, CC, CC, 0, 0, 1, 0);
    wconv2<<<dim3(KVH*DH/64, CC/64, 1), cb>>>(wk, wqkvt + (size_t)CC*CC, CC, KVH*DH, 0, 0, 1, 0);
    wconv2<<<dim3(KVH*DH/64, CC/64, 1), cb>>>(wv, wqkvt + (size_t)(CC+KVH*DH)*CC, CC, KVH*DH, 0, 0, 1, 0);
    wconv2<<<dim3(CC/64,  CC/64, 1), cb>>>(wo,  wot,  CC, CC, 0, 0, 1, 0);
    wconv2<<<dim3(FF/64,  CC/64, 1), cb>>>(sw1, sw12t, CC, FF, 0, 0, 2, 0);
    wconv2<<<dim3(FF/64,  CC/64, 1), cb>>>(sw2, sw12t, CC, FF, 0, 0, 2, 1);
    wconv2<<<dim3(CC/64,  FF/64, 1), cb>>>(sw3, sw3t, FF, CC, 0, 0, 1, 0);
    wconv2<<<dim3(FF/64,  CC/64, EE), cb>>>(ew1, ew12t, CC, FF, (long)CC*FF, (long)2*FF*CC, 2, 0);
    wconv2<<<dim3(FF/64,  CC/64, EE), cb>>>(ew2, ew12t, CC, FF, (long)CC*FF, (long)2*FF*CC, 2, 1);
    wconv2<<<dim3(CC/64,  FF/64, EE), cb>>>(ew3, ew3t, FF, CC, (long)FF*CC, (long)CC*FF, 1, 0);

    // 1) pre-attn norm
    rmsnorm_kernel<<<NTOK, 256>>>(x, ln1, nullptr, xnb);
    // 2) fused QKV projection
    gemm_mma<<<dim3(QKVN/128, NTOK/128), 256>>>(xnb, wqkvt, qkv, QKVN, CC);
    // 3) RoPE
    rope_kernel<<<(NTOK * HH * 32 + 255) / 256, 256>>>(qkv, HH, 0);
    rope_kernel<<<(NTOK * KVH * 32 + 255) / 256, 256>>>(qkv, KVH, CC);
    // 4) attention (tensor core)
    attn_mma<<<dim3(TT/64, HH, BB), 128>>>(qkv, aob);
    // 5) output projection + ReZero residual
    gemm_mma<<<dim3(CC/128, NTOK/128), 256>>>(aob, wot, proj, CC, CC);
    resadd_kernel<<<(OUT_MAIN + 255) / 256, 256>>>(x, proj, a_attn, h);
    // 6) post-attn norm
    rmsnorm_kernel<<<NTOK, 256>>>(h, ln2, xf, xfb);
    // 7) routing + aux + compaction
    route_kernel<<<NTOK / 4, 128>>>(xf, gatew);
    aux_kernel<<<1, 256>>>();
    zero_cnt_kernel<<<1, 32>>>();
    count_kernel<<<(NTOK + 255) / 256, 256>>>();
    offsets_kernel<<<1, 32>>>();
    assign_kernel<<<(NTOK + 255) / 256, 256>>>();
    // 8) shared expert: fused w12+SwiGLU, then w3
    gemm_swiglu<<<dim3(2*FF/128, NTOK/128), 256>>>(xfb, sw12t, g1b, 2*FF, CC);
    gemm_mma<<<dim3(CC/128, NTOK/128), 256>>>(g1b, sw3t, moe, CC, FF);
    // 9) routed experts, batched
    gather_all_kernel<<<ECAP, 128>>>(xgb, xfb);
    gemm_moe_swiglu<<<dim3(2*FF/128, ECAP/128), 256>>>(xgb, ew12t, g1b, 2*FF, CC, (long)2*FF*CC);
    gemm_moe<<<dim3(CC/128, ECAP/128), 256>>>(g1b, ew3t, eo, CC, FF, (long)CC*FF);
    // 10) final combine + aux scalar
    final_kernel<<<NTOK, 256>>>(h, moe, eo, a_moe, out);
    if (out_size > OUT_MAIN) auxwrite_kernel<<<1, 1>>>(out);
}